// round 15
// baseline (speedup 1.0000x reference)
#include <cuda_runtime.h>
#include <cuda_fp16.h>
#include <cstdint>
#include <cstddef>
#include <math.h>

// ============================================================================
// out = x @ (irfft(U)·S @ irfft(V)).T + bias
// G1 radix-4 folded, G3 radix-2 folded. Plain fp16 GEMMs with fp32
// accumulators (error model: 1.9e-4/dropped term, RSS -> ~5.6e-4 measured).
// Power-of-2 scaling keeps operands fp16-normal: bases x2^10, Y/T32 at 2^10,
// Z at 2^20, G4 epilogue x2^-20.
// Round 15: trig via root-of-unity tables (kills ~25us of MUFU in prep).
// ============================================================================

static constexpr double PI_D = 3.141592653589793238462643383279502884;

// ---------------- device scratch ---------------------------------------------
__device__ __align__(128) __half g_XQ[4ull * 1024 * 1088];
__device__ __align__(128) __half g_BQ[4ull * 512 * 1088];
__device__ __align__(128) __half g_GH[2ull * 512 * 1088];
__device__ __align__(128) __half g_TF[2ull * 1024 * 1088];
__device__ __align__(128) __half g_VTh[2048ull * 2048];
__device__ __align__(128) __half g_Uh[4096ull * 1024];
__device__ __align__(128) __half g_Yh[1024ull * 2048];
__device__ __align__(128) __half g_Zh[1024ull * 1024];
__device__ __align__(128) float g_T32[1024ull * 2048];
__device__ __align__(16) float2 g_tab4096[4096];
__device__ __align__(16) float2 g_tab2048[2048];

static constexpr int KQ = 1088;

// ---------------- helpers ------------------------------------------------------
__device__ __forceinline__ uint32_t s2u(const void* p) {
    uint32_t a;
    asm("{ .reg .u64 t; cvta.to.shared.u64 t, %1; cvt.u32.u64 %0, t; }"
        : "=r"(a) : "l"(p));
    return a;
}
__device__ __forceinline__ void cpa16(uint32_t dst, const void* src) {
    asm volatile("cp.async.cg.shared.global [%0], [%1], 16;"
                 :: "r"(dst), "l"(src) : "memory");
}
#define CP_COMMIT() asm volatile("cp.async.commit_group;" ::: "memory")
#define CP_WAIT1()  asm volatile("cp.async.wait_group 1;" ::: "memory")

__device__ __forceinline__ uint32_t swz(uint32_t r, uint32_t cb) {
    return r * 128u + (cb ^ ((r & 7u) << 4));
}
__device__ __forceinline__ uint32_t pack_h(__half a, __half b) {
    __half2 t = __halves2half2(a, b);
    return *reinterpret_cast<uint32_t*>(&t);
}
__device__ __forceinline__ void pack8h(const float* v, uint4& H) {
    __half h[8];
#pragma unroll
    for (int e = 0; e < 8; e++) h[e] = __float2half_rn(v[e]);
    H = *reinterpret_cast<uint4*>(h);
}
#define LDSM4(r, addr)                                                        \
    asm volatile("ldmatrix.sync.aligned.m8n8.x4.shared.b16 {%0,%1,%2,%3}, [%4];" \
                 : "=r"((r)[0]), "=r"((r)[1]), "=r"((r)[2]), "=r"((r)[3])     \
                 : "r"(addr))
#define HMMA(acc, a, b0, b1)                                                  \
    asm volatile(                                                             \
        "mma.sync.aligned.m16n8k16.row.col.f32.f16.f16.f32 "                  \
        "{%0,%1,%2,%3}, {%4,%5,%6,%7}, {%8,%9}, {%0,%1,%2,%3};"               \
        : "+f"((acc)[0]), "+f"((acc)[1]), "+f"((acc)[2]), "+f"((acc)[3])      \
        : "r"((a)[0]), "r"((a)[1]), "r"((a)[2]), "r"((a)[3]), "r"(b0), "r"(b1))

// ---------------- tiny table kernel ----------------------------------------------
__global__ void gen_tables_kernel(float2* __restrict__ t4, float2* __restrict__ t2) {
    int t = blockIdx.x * blockDim.x + threadIdx.x;
    if (t < 4096) {
        double a = (2.0 * PI_D / 4096.0) * (double)t;
        t4[t] = make_float2((float)cos(a), (float)sin(a));
    }
    if (t < 2048) {
        double a = (2.0 * PI_D / 2048.0) * (double)t;
        t2[t] = make_float2((float)cos(a), (float)sin(a));
    }
}

// ---------------- fused prep kernel ---------------------------------------------
static constexpr int PB_BQ = 1088;
static constexpr int PB_GH = PB_BQ + 544;
static constexpr int PB_FX = PB_GH + 544;
static constexpr int PB_VT = PB_FX + 2048;
static constexpr int PB_U  = PB_VT + 2048;

__global__ void __launch_bounds__(256)
prep_kernel(const float* __restrict__ x,
            const float* __restrict__ U_real, const float* __restrict__ U_imag,
            const float* __restrict__ S,
            const float* __restrict__ Vt_real, const float* __restrict__ Vt_imag,
            const float2* __restrict__ t4, const float2* __restrict__ t2,
            __half* __restrict__ BQ, __half* __restrict__ GH,
            __half* __restrict__ XQ,
            __half* __restrict__ VTh, __half* __restrict__ Uh) {
    const int blk = blockIdx.x;
    const int thr = threadIdx.x;

    if (blk < PB_GH) {
        // ---- trig bases via table lookup, scaled x2^10 ----
        bool isBQ = (blk < PB_BQ);
        int u = (isBQ ? blk : (blk - PB_BQ)) * 256 + thr;
        int jv8 = u % 136;
        int kk = (u / 136) & 511;
        int z = u / (136 * 512);
        if (!isBQ && z >= 2) return;
        if (isBQ && z >= 4) return;
        int jv = jv8 * 8;
        int n = isBQ ? 4096 : 2048;
        int k = isBQ ? (2 * kk + (z & 1)) : kk;
        bool is_cos = isBQ ? (z < 2) : (z == 0);
        float ww = ((k == 0) ? 1024.0f : 2048.0f) / (float)n;  // x2^10
        const float2* tab = isBQ ? t4 : t2;
        int mask = n - 1;
        float v[8];
#pragma unroll
        for (int e = 0; e < 8; e++) {
            int j = jv + e;
            float w = 0.0f;
            if (j <= 1024) {
                float2 cs = tab[(j * k) & mask];
                w = is_cos ? ww * cs.x : -ww * cs.y;
            }
            v[e] = w;
        }
        uint4 H;
        pack8h(v, H);
        __half* base = isBQ ? BQ : GH;
        size_t off = ((size_t)z * 512 + kk) * KQ + jv;
        *reinterpret_cast<uint4*>(base + off) = H;
    } else if (blk < PB_FX) {
        // ---- foldX ----
        int t = (blk - PB_GH) * 256 + thr;
        if (t >= 1024 * 136) return;
        int r = t / 136;
        int jv = (t % 136) * 8;
        const float* xr = x + (size_t)r * 4096;
        float vee[8], veo[8], voe[8], voo[8];
#pragma unroll
        for (int e = 0; e < 8; e++) {
            int j = jv + e;
            float ee = 0, eo = 0, oe = 0, oo = 0;
            if (j == 0) {
                float a = xr[0], nq = xr[2048];
                ee = a + nq; eo = a - nq;
            } else if (j < 1024) {
                float a = xr[j], b = xr[4096 - j], c = xr[2048 - j], d = xr[2048 + j];
                float E = a + b, O = a - b, E2 = c + d, O2 = c - d;
                ee = E + E2; eo = E - E2; oe = O - O2; oo = O + O2;
            } else if (j == 1024) {
                float a = xr[1024], b = xr[3072];
                float E = a + b, O = a - b;
                ee = E; eo = E; oe = O; oo = O;
            }
            vee[e] = ee; veo[e] = eo; voe[e] = oe; voo[e] = oo;
        }
        uint4 H;
        size_t rb = (size_t)r * KQ + jv;
        size_t plane = 1024ull * KQ;
        pack8h(vee, H);
        *reinterpret_cast<uint4*>(XQ + 0 * plane + rb) = H;
        pack8h(veo, H);
        *reinterpret_cast<uint4*>(XQ + 1 * plane + rb) = H;
        pack8h(voe, H);
        *reinterpret_cast<uint4*>(XQ + 2 * plane + rb) = H;
        pack8h(voo, H);
        *reinterpret_cast<uint4*>(XQ + 3 * plane + rb) = H;
    } else if (blk < PB_VT) {
        // ---- splitVT (S folded, column-permuted) ----
        int t = (blk - PB_FX) * 256 + thr;
        if (t >= 2048 * 256) return;
        int l = t >> 8;
        int c0 = (t & 255) * 8;
        int q = c0 >> 9;
        const float* src = ((q < 2) ? Vt_real : Vt_imag) + (size_t)l * 1024;
        float s = S[l];
        float v[8];
#pragma unroll
        for (int e = 0; e < 8; e++) {
            int k = (((c0 & 511) + e) << 1) | (q & 1);
            v[e] = src[k] * s;
        }
        uint4 H;
        pack8h(v, H);
        *reinterpret_cast<uint4*>(VTh + (size_t)l * 2048 + c0) = H;
    } else {
        // ---- splitU ----
        int t = (blk - PB_VT) * 256 + thr;
        if (t >= 4096 * 128) return;
        int r = t >> 7;
        int c0 = (t & 127) * 8;
        const float* src = ((c0 >> 9) ? U_imag : U_real) + (size_t)r * 512;
        float v[8];
#pragma unroll
        for (int e = 0; e < 8; e++) v[e] = src[(c0 & 511) + e];
        uint4 H;
        pack8h(v, H);
        *reinterpret_cast<uint4*>(Uh + (size_t)r * 1024 + c0) = H;
    }
}

// ---------------- foldT (depends on G2; values at 2^10 scale) --------------------
__global__ void foldT_kernel(const float* __restrict__ T,
                             __half* __restrict__ TF) {
    int t = blockIdx.x * blockDim.x + threadIdx.x;
    if (t >= 1024 * 136) return;
    int r = t / 136;
    int jv = (t % 136) * 8;
    const float* Tr = T + (size_t)r * 2048;
    float vc[8], vs[8];
#pragma unroll
    for (int e = 0; e < 8; e++) {
        int j = jv + e;
        float c = 0, s = 0;
        if (j == 0) {
            c = Tr[0];
        } else if (j < 1024) {
            float a = Tr[j], b = Tr[2048 - j];
            c = a + b; s = a - b;
        } else if (j == 1024) {
            c = Tr[1024];
        }
        vc[e] = c; vs[e] = s;
    }
    uint4 H;
    size_t rb = (size_t)r * KQ + jv;
    size_t plane = 1024ull * KQ;
    pack8h(vc, H);
    *reinterpret_cast<uint4*>(TF + 0 * plane + rb) = H;
    pack8h(vs, H);
    *reinterpret_cast<uint4*>(TF + 1 * plane + rb) = H;
}

// ---------------- HMMA GEMM (single pass: C = Ah @ Bh^T) -------------------------
struct GP4 {
    const __half* Ah[4];
    const __half* Bh[4];
};

// EPI=0: write fp16 C. EPI=1: write fp32 C*oscale + bias(col).
template <int BN, int EPI>
__global__ void __launch_bounds__(128, 2)
hmma_gemm(GP4 gp, int bpq, int K,
          const float* __restrict__ bias, float oscale,
          __half* __restrict__ Ch, float* __restrict__ Cf, int ldc) {
    constexpr int NW = BN / 32;
    constexpr int ATILE = 16384;
    constexpr int BTILE = BN * 128;
    constexpr uint32_t STAGE = ATILE + BTILE;   // 24576 for BN=64
    constexpr int NTHR = 128;

    extern __shared__ char dyn[];
    __shared__ float sparam[BN];

    const int tid = threadIdx.x;
    const int wid = tid >> 5;
    const int lane = tid & 31;
    const int setId = blockIdx.x / bpq;
    const int jb = blockIdx.x % bpq;
    const int i0 = blockIdx.y * 128;
    const int j0g = blockIdx.x * BN;
    const uint32_t sbase = s2u(dyn);

    const __half* Ah = gp.Ah[setId];
    const __half* Bh = gp.Bh[setId];

    if (EPI == 1)
        for (int i = tid; i < BN; i += NTHR) sparam[i] = bias ? bias[j0g + i] : 0.0f;

    const int nch = K >> 6;

    const int arow = lane & 15;
    const int acol = lane & 16;
    const int brow = (lane & 7) + ((lane & 16) >> 1);
    const int bcol = (lane & 8) << 1;

    const int m0 = (wid / NW) * 64;
    const int n0 = (wid % NW) * 32;

    float acc[4][4][4];
#pragma unroll
    for (int a = 0; a < 4; a++)
#pragma unroll
        for (int b = 0; b < 4; b++)
#pragma unroll
            for (int c = 0; c < 4; c++) acc[a][b][c] = 0.0f;

    auto load_stage = [&](int c, int stg) {
        const uint32_t sb = sbase + (uint32_t)stg * STAGE;
        const int k0 = c << 6;
        const __half* gAh = Ah + (size_t)i0 * K + k0;
        const __half* gBh = Bh + (size_t)jb * BN * K + k0;
#pragma unroll
        for (int it = 0; it < 8; it++) {
            int s = tid + it * NTHR;
            int r = s >> 3, cc = s & 7;
            cpa16(sb + swz(r, cc * 16), gAh + (size_t)r * K + cc * 8);
        }
#pragma unroll
        for (int it = 0; it < BN * 8 / NTHR; it++) {
            int s = tid + it * NTHR;
            int r = s >> 3, cc = s & 7;
            cpa16(sb + ATILE + swz(r, cc * 16), gBh + (size_t)r * K + cc * 8);
        }
    };

    load_stage(0, 0); CP_COMMIT();
    if (nch > 1) load_stage(1, 1);
    CP_COMMIT();

    for (int c = 0; c < nch; c++) {
        CP_WAIT1();
        __syncthreads();

        const uint32_t sb = sbase + (uint32_t)(c & 1) * STAGE;
        const uint32_t sAh = sb;
        const uint32_t sBh = sb + ATILE;

#pragma unroll
        for (int kk = 0; kk < 4; kk++) {
            const uint32_t kb = kk * 32;

            uint32_t aH[4][4], bH[2][4];
#pragma unroll
            for (int mi = 0; mi < 4; mi++)
                LDSM4(aH[mi], sAh + swz(m0 + mi * 16 + arow, kb + acol));
#pragma unroll
            for (int nb = 0; nb < 2; nb++)
                LDSM4(bH[nb], sBh + swz(n0 + nb * 16 + brow, kb + bcol));

#pragma unroll
            for (int mi = 0; mi < 4; mi++)
#pragma unroll
                for (int ni = 0; ni < 4; ni++)
                    HMMA(acc[mi][ni], aH[mi],
                         bH[ni >> 1][(ni & 1) * 2], bH[ni >> 1][(ni & 1) * 2 + 1]);
        }
        __syncthreads();
        if (c + 2 < nch) load_stage(c + 2, c & 1);
        CP_COMMIT();
    }

    // ---- epilogue ----
    const int tg = lane >> 2;
    const int ti = lane & 3;
#pragma unroll
    for (int mi = 0; mi < 4; mi++) {
#pragma unroll
        for (int ni = 0; ni < 4; ni++) {
            const int cl = n0 + ni * 8 + 2 * ti;
            const int gj = j0g + cl;
#pragma unroll
            for (int h = 0; h < 2; h++) {
                const int gi = i0 + m0 + mi * 16 + tg + h * 8;
                const float c0 = acc[mi][ni][2 * h];
                const float c1 = acc[mi][ni][2 * h + 1];
                if (EPI == 0) {
                    *reinterpret_cast<uint32_t*>(Ch + (size_t)gi * ldc + gj) =
                        pack_h(__float2half_rn(c0), __float2half_rn(c1));
                } else {
                    float2 v = make_float2(c0 * oscale + sparam[cl],
                                           c1 * oscale + sparam[cl + 1]);
                    *reinterpret_cast<float2*>(Cf + (size_t)gi * ldc + gj) = v;
                }
            }
        }
    }
}

// ---------------- launcher ---------------------------------------------------------
extern "C" void kernel_launch(void* const* d_in, const int* in_sizes, int n_in,
                              void* d_out, int out_size) {
    const float* x       = (const float*)d_in[0];
    const float* U_real  = (const float*)d_in[1];
    const float* U_imag  = (const float*)d_in[2];
    const float* S       = (const float*)d_in[3];
    const float* Vt_real = (const float*)d_in[4];
    const float* Vt_imag = (const float*)d_in[5];
    const float* bias    = (const float*)d_in[6];
    float* out           = (float*)d_out;

#define GA(v, s) void* v; cudaGetSymbolAddress(&v, s)
    GA(XQ, g_XQ); GA(BQ, g_BQ); GA(GH, g_GH); GA(TF, g_TF);
    GA(VTh, g_VTh); GA(Uh, g_Uh);
    GA(Yh, g_Yh); GA(Zh, g_Zh);
    GA(T32, g_T32);
    GA(t4, g_tab4096); GA(t2, g_tab2048);
#undef GA

    constexpr int SMEM = 2 * (16384 + 64 * 128);  // 49152
    cudaFuncSetAttribute(hmma_gemm<64, 0>, cudaFuncAttributeMaxDynamicSharedMemorySize, SMEM);
    cudaFuncSetAttribute(hmma_gemm<64, 1>, cudaFuncAttributeMaxDynamicSharedMemorySize, SMEM);

    typedef const __half* HP;
    const size_t PX = 1024ull * KQ;
    const size_t PB = 512ull * KQ;
    constexpr float DESCALE20 = 1.0f / 1048576.0f;  // 2^-20

    // ---- tables (tiny) + fused prep ----
    gen_tables_kernel<<<16, 256>>>((float2*)t4, (float2*)t2);
    prep_kernel<<<PB_U, 256>>>(x, U_real, U_imag, S, Vt_real, Vt_imag,
                               (const float2*)t4, (const float2*)t2,
                               (__half*)BQ, (__half*)GH, (__half*)XQ,
                               (__half*)VTh, (__half*)Uh);

    // ---- G1: Y(2^10) = 4 quarter GEMMs (1024 x 2048, K=1088) ----
    {
        GP4 gp;
        HP xq = (HP)XQ, bq = (HP)BQ;
        for (int q = 0; q < 4; q++) {
            gp.Ah[q] = xq + q * PX;
            gp.Bh[q] = bq + q * PB;
        }
        hmma_gemm<64, 0><<<dim3(32, 8), 128, SMEM>>>(
            gp, 8, KQ, nullptr, 1.0f, (__half*)Yh, nullptr, 2048);
    }
    // ---- G2: T32(2^10) = Y @ (S*VTperm)^T (1024 x 2048, K=2048), fp32 out ----
    {
        GP4 gp;
        for (int q = 0; q < 4; q++) {
            gp.Ah[q] = (HP)Yh; gp.Bh[q] = (HP)VTh;
        }
        hmma_gemm<64, 1><<<dim3(32, 8), 128, SMEM>>>(
            gp, 32, 2048, nullptr, 1.0f, nullptr, (float*)T32, 2048);
    }
    // ---- fold T ----
    foldT_kernel<<<(1024 * 136 + 255) / 256, 256>>>((const float*)T32, (__half*)TF);
    // ---- G3: Z(2^20) = 2 half GEMMs (1024 x 1024, K=1088) ----
    {
        GP4 gp;
        HP tf = (HP)TF, gh = (HP)GH;
        for (int q = 0; q < 4; q++) {
            int h2 = (q > 1) ? 1 : q;
            gp.Ah[q] = tf + h2 * PX;
            gp.Bh[q] = gh + h2 * PB;
        }
        hmma_gemm<64, 0><<<dim3(16, 8), 128, SMEM>>>(
            gp, 8, KQ, nullptr, 1.0f, (__half*)Zh, nullptr, 1024);
    }
    // ---- G4: out = Z @ U^T * 2^-20 + bias (1024 x 4096, K=1024) ----
    {
        GP4 gp;
        for (int q = 0; q < 4; q++) {
            gp.Ah[q] = (HP)Zh; gp.Bh[q] = (HP)Uh;
        }
        hmma_gemm<64, 1><<<dim3(64, 8), 128, SMEM>>>(
            gp, 64, 1024, bias, DESCALE20, nullptr, (float*)out, 4096);
    }
}

// round 16
// speedup vs baseline: 1.1182x; 1.1182x over previous
#include <cuda_runtime.h>
#include <cuda_fp16.h>
#include <cstdint>
#include <cstddef>
#include <math.h>

// ============================================================================
// out = x @ (irfft(U)·S @ irfft(V)).T + bias
// G1 radix-4 folded, G3 radix-2 folded. Plain fp16 GEMMs with fp32 accums
// (validated error model: ~5.6e-4). Power-of-2 scaling: bases x2^10, Y/T32 at
// 2^10, Z at 2^20, G4 epilogue x2^-20.
// Round 16: 3-stage cp.async ring, ONE sync per chunk, loads issued 2 chunks
// ahead so they overlap compute (fixes 45% tensor bubble seen in G2 profile).
// ============================================================================

static constexpr double PI_D = 3.141592653589793238462643383279502884;

// ---------------- device scratch ---------------------------------------------
__device__ __align__(128) __half g_XQ[4ull * 1024 * 1088];
__device__ __align__(128) __half g_BQ[4ull * 512 * 1088];
__device__ __align__(128) __half g_GH[2ull * 512 * 1088];
__device__ __align__(128) __half g_TF[2ull * 1024 * 1088];
__device__ __align__(128) __half g_VTh[2048ull * 2048];
__device__ __align__(128) __half g_Uh[4096ull * 1024];
__device__ __align__(128) __half g_Yh[1024ull * 2048];
__device__ __align__(128) __half g_Zh[1024ull * 1024];
__device__ __align__(128) float g_T32[1024ull * 2048];

static constexpr int KQ = 1088;

// ---------------- helpers ------------------------------------------------------
__device__ __forceinline__ uint32_t s2u(const void* p) {
    uint32_t a;
    asm("{ .reg .u64 t; cvta.to.shared.u64 t, %1; cvt.u32.u64 %0, t; }"
        : "=r"(a) : "l"(p));
    return a;
}
__device__ __forceinline__ void cpa16(uint32_t dst, const void* src) {
    asm volatile("cp.async.cg.shared.global [%0], [%1], 16;"
                 :: "r"(dst), "l"(src) : "memory");
}
#define CP_COMMIT() asm volatile("cp.async.commit_group;" ::: "memory")
#define CP_WAIT1()  asm volatile("cp.async.wait_group 1;" ::: "memory")

__device__ __forceinline__ uint32_t swz(uint32_t r, uint32_t cb) {
    return r * 128u + (cb ^ ((r & 7u) << 4));
}
__device__ __forceinline__ uint32_t pack_h(__half a, __half b) {
    __half2 t = __halves2half2(a, b);
    return *reinterpret_cast<uint32_t*>(&t);
}
__device__ __forceinline__ void pack8h(const float* v, uint4& H) {
    __half h[8];
#pragma unroll
    for (int e = 0; e < 8; e++) h[e] = __float2half_rn(v[e]);
    H = *reinterpret_cast<uint4*>(h);
}
#define LDSM4(r, addr)                                                        \
    asm volatile("ldmatrix.sync.aligned.m8n8.x4.shared.b16 {%0,%1,%2,%3}, [%4];" \
                 : "=r"((r)[0]), "=r"((r)[1]), "=r"((r)[2]), "=r"((r)[3])     \
                 : "r"(addr))
#define HMMA(acc, a, b0, b1)                                                  \
    asm volatile(                                                             \
        "mma.sync.aligned.m16n8k16.row.col.f32.f16.f16.f32 "                  \
        "{%0,%1,%2,%3}, {%4,%5,%6,%7}, {%8,%9}, {%0,%1,%2,%3};"               \
        : "+f"((acc)[0]), "+f"((acc)[1]), "+f"((acc)[2]), "+f"((acc)[3])      \
        : "r"((a)[0]), "r"((a)[1]), "r"((a)[2]), "r"((a)[3]), "r"(b0), "r"(b1))

// ---------------- fused prep kernel (round-14 sincosf version) -------------------
static constexpr int PB_BQ = 1088;
static constexpr int PB_GH = PB_BQ + 544;
static constexpr int PB_FX = PB_GH + 544;
static constexpr int PB_VT = PB_FX + 2048;
static constexpr int PB_U  = PB_VT + 2048;

__global__ void __launch_bounds__(256)
prep_kernel(const float* __restrict__ x,
            const float* __restrict__ U_real, const float* __restrict__ U_imag,
            const float* __restrict__ S,
            const float* __restrict__ Vt_real, const float* __restrict__ Vt_imag,
            __half* __restrict__ BQ, __half* __restrict__ GH,
            __half* __restrict__ XQ,
            __half* __restrict__ VTh, __half* __restrict__ Uh) {
    const int blk = blockIdx.x;
    const int thr = threadIdx.x;

    if (blk < PB_GH) {
        bool isBQ = (blk < PB_BQ);
        int u = (isBQ ? blk : (blk - PB_BQ)) * 256 + thr;
        int jv8 = u % 136;
        int kk = (u / 136) & 511;
        int z = u / (136 * 512);
        if (!isBQ && z >= 2) return;
        if (isBQ && z >= 4) return;
        int jv = jv8 * 8;
        int n = isBQ ? 4096 : 2048;
        int k = isBQ ? (2 * kk + (z & 1)) : kk;
        bool is_cos = isBQ ? (z < 2) : (z == 0);
        float ww = ((k == 0) ? 1024.0f : 2048.0f) / (float)n;  // x2^10
        float step = (float)(2.0 * PI_D / n);
        int mask = n - 1;
        float v[8];
#pragma unroll
        for (int e = 0; e < 8; e++) {
            int j = jv + e;
            float w = 0.0f;
            if (j <= 1024) {
                int idx = (j * k) & mask;
                float sv, cv;
                sincosf(step * (float)idx, &sv, &cv);
                w = is_cos ? ww * cv : -ww * sv;
            }
            v[e] = w;
        }
        uint4 H;
        pack8h(v, H);
        __half* base = isBQ ? BQ : GH;
        size_t off = ((size_t)z * 512 + kk) * KQ + jv;
        *reinterpret_cast<uint4*>(base + off) = H;
    } else if (blk < PB_FX) {
        int t = (blk - PB_GH) * 256 + thr;
        if (t >= 1024 * 136) return;
        int r = t / 136;
        int jv = (t % 136) * 8;
        const float* xr = x + (size_t)r * 4096;
        float vee[8], veo[8], voe[8], voo[8];
#pragma unroll
        for (int e = 0; e < 8; e++) {
            int j = jv + e;
            float ee = 0, eo = 0, oe = 0, oo = 0;
            if (j == 0) {
                float a = xr[0], nq = xr[2048];
                ee = a + nq; eo = a - nq;
            } else if (j < 1024) {
                float a = xr[j], b = xr[4096 - j], c = xr[2048 - j], d = xr[2048 + j];
                float E = a + b, O = a - b, E2 = c + d, O2 = c - d;
                ee = E + E2; eo = E - E2; oe = O - O2; oo = O + O2;
            } else if (j == 1024) {
                float a = xr[1024], b = xr[3072];
                float E = a + b, O = a - b;
                ee = E; eo = E; oe = O; oo = O;
            }
            vee[e] = ee; veo[e] = eo; voe[e] = oe; voo[e] = oo;
        }
        uint4 H;
        size_t rb = (size_t)r * KQ + jv;
        size_t plane = 1024ull * KQ;
        pack8h(vee, H);
        *reinterpret_cast<uint4*>(XQ + 0 * plane + rb) = H;
        pack8h(veo, H);
        *reinterpret_cast<uint4*>(XQ + 1 * plane + rb) = H;
        pack8h(voe, H);
        *reinterpret_cast<uint4*>(XQ + 2 * plane + rb) = H;
        pack8h(voo, H);
        *reinterpret_cast<uint4*>(XQ + 3 * plane + rb) = H;
    } else if (blk < PB_VT) {
        int t = (blk - PB_FX) * 256 + thr;
        if (t >= 2048 * 256) return;
        int l = t >> 8;
        int c0 = (t & 255) * 8;
        int q = c0 >> 9;
        const float* src = ((q < 2) ? Vt_real : Vt_imag) + (size_t)l * 1024;
        float s = S[l];
        float v[8];
#pragma unroll
        for (int e = 0; e < 8; e++) {
            int k = (((c0 & 511) + e) << 1) | (q & 1);
            v[e] = src[k] * s;
        }
        uint4 H;
        pack8h(v, H);
        *reinterpret_cast<uint4*>(VTh + (size_t)l * 2048 + c0) = H;
    } else {
        int t = (blk - PB_VT) * 256 + thr;
        if (t >= 4096 * 128) return;
        int r = t >> 7;
        int c0 = (t & 127) * 8;
        const float* src = ((c0 >> 9) ? U_imag : U_real) + (size_t)r * 512;
        float v[8];
#pragma unroll
        for (int e = 0; e < 8; e++) v[e] = src[(c0 & 511) + e];
        uint4 H;
        pack8h(v, H);
        *reinterpret_cast<uint4*>(Uh + (size_t)r * 1024 + c0) = H;
    }
}

// ---------------- foldT (depends on G2; values at 2^10 scale) --------------------
__global__ void foldT_kernel(const float* __restrict__ T,
                             __half* __restrict__ TF) {
    int t = blockIdx.x * blockDim.x + threadIdx.x;
    if (t >= 1024 * 136) return;
    int r = t / 136;
    int jv = (t % 136) * 8;
    const float* Tr = T + (size_t)r * 2048;
    float vc[8], vs[8];
#pragma unroll
    for (int e = 0; e < 8; e++) {
        int j = jv + e;
        float c = 0, s = 0;
        if (j == 0) {
            c = Tr[0];
        } else if (j < 1024) {
            float a = Tr[j], b = Tr[2048 - j];
            c = a + b; s = a - b;
        } else if (j == 1024) {
            c = Tr[1024];
        }
        vc[e] = c; vs[e] = s;
    }
    uint4 H;
    size_t rb = (size_t)r * KQ + jv;
    size_t plane = 1024ull * KQ;
    pack8h(vc, H);
    *reinterpret_cast<uint4*>(TF + 0 * plane + rb) = H;
    pack8h(vs, H);
    *reinterpret_cast<uint4*>(TF + 1 * plane + rb) = H;
}

// ---------------- HMMA GEMM (single pass, 3-stage ring, 1 sync/chunk) ------------
struct GP4 {
    const __half* Ah[4];
    const __half* Bh[4];
};

// EPI=0: write fp16 C. EPI=1: write fp32 C*oscale + bias(col).
template <int BN, int EPI>
__global__ void __launch_bounds__(128, 2)
hmma_gemm(GP4 gp, int bpq, int K,
          const float* __restrict__ bias, float oscale,
          __half* __restrict__ Ch, float* __restrict__ Cf, int ldc) {
    constexpr int NW = BN / 32;
    constexpr int ATILE = 16384;
    constexpr int BTILE = BN * 128;
    constexpr uint32_t STAGE = ATILE + BTILE;   // 24576 for BN=64
    constexpr int NTHR = 128;

    extern __shared__ char dyn[];
    __shared__ float sparam[BN];

    const int tid = threadIdx.x;
    const int wid = tid >> 5;
    const int lane = tid & 31;
    const int setId = blockIdx.x / bpq;
    const int jb = blockIdx.x % bpq;
    const int i0 = blockIdx.y * 128;
    const int j0g = blockIdx.x * BN;
    const uint32_t sbase = s2u(dyn);

    const __half* Ah = gp.Ah[setId];
    const __half* Bh = gp.Bh[setId];

    if (EPI == 1)
        for (int i = tid; i < BN; i += NTHR) sparam[i] = bias ? bias[j0g + i] : 0.0f;

    const int nch = K >> 6;

    const int arow = lane & 15;
    const int acol = lane & 16;
    const int brow = (lane & 7) + ((lane & 16) >> 1);
    const int bcol = (lane & 8) << 1;

    const int m0 = (wid / NW) * 64;
    const int n0 = (wid % NW) * 32;

    float acc[4][4][4];
#pragma unroll
    for (int a = 0; a < 4; a++)
#pragma unroll
        for (int b = 0; b < 4; b++)
#pragma unroll
            for (int c = 0; c < 4; c++) acc[a][b][c] = 0.0f;

    auto load_stage = [&](int c, int stg) {
        const uint32_t sb = sbase + (uint32_t)stg * STAGE;
        const int k0 = c << 6;
        const __half* gAh = Ah + (size_t)i0 * K + k0;
        const __half* gBh = Bh + (size_t)jb * BN * K + k0;
#pragma unroll
        for (int it = 0; it < 8; it++) {
            int s = tid + it * NTHR;
            int r = s >> 3, cc = s & 7;
            cpa16(sb + swz(r, cc * 16), gAh + (size_t)r * K + cc * 8);
        }
#pragma unroll
        for (int it = 0; it < BN * 8 / NTHR; it++) {
            int s = tid + it * NTHR;
            int r = s >> 3, cc = s & 7;
            cpa16(sb + ATILE + swz(r, cc * 16), gBh + (size_t)r * K + cc * 8);
        }
    };

    load_stage(0, 0); CP_COMMIT();
    if (nch > 1) load_stage(1, 1);
    CP_COMMIT();

    for (int c = 0; c < nch; c++) {
        CP_WAIT1();           // chunk c landed (<=1 group pending)
        __syncthreads();      // all warps done reading stage (c-1)%3 == (c+2)%3

        // issue chunk c+2 BEFORE compute — overlaps this chunk's MMAs
        if (c + 2 < nch) load_stage(c + 2, (c + 2) % 3);
        CP_COMMIT();

        const uint32_t sb = sbase + (uint32_t)(c % 3) * STAGE;
        const uint32_t sAh = sb;
        const uint32_t sBh = sb + ATILE;

#pragma unroll
        for (int kk = 0; kk < 4; kk++) {
            const uint32_t kb = kk * 32;

            uint32_t aH[4][4], bH[2][4];
#pragma unroll
            for (int mi = 0; mi < 4; mi++)
                LDSM4(aH[mi], sAh + swz(m0 + mi * 16 + arow, kb + acol));
#pragma unroll
            for (int nb = 0; nb < 2; nb++)
                LDSM4(bH[nb], sBh + swz(n0 + nb * 16 + brow, kb + bcol));

#pragma unroll
            for (int mi = 0; mi < 4; mi++)
#pragma unroll
                for (int ni = 0; ni < 4; ni++)
                    HMMA(acc[mi][ni], aH[mi],
                         bH[ni >> 1][(ni & 1) * 2], bH[ni >> 1][(ni & 1) * 2 + 1]);
        }
    }

    // ---- epilogue ----
    const int tg = lane >> 2;
    const int ti = lane & 3;
#pragma unroll
    for (int mi = 0; mi < 4; mi++) {
#pragma unroll
        for (int ni = 0; ni < 4; ni++) {
            const int cl = n0 + ni * 8 + 2 * ti;
            const int gj = j0g + cl;
#pragma unroll
            for (int h = 0; h < 2; h++) {
                const int gi = i0 + m0 + mi * 16 + tg + h * 8;
                const float c0 = acc[mi][ni][2 * h];
                const float c1 = acc[mi][ni][2 * h + 1];
                if (EPI == 0) {
                    *reinterpret_cast<uint32_t*>(Ch + (size_t)gi * ldc + gj) =
                        pack_h(__float2half_rn(c0), __float2half_rn(c1));
                } else {
                    float2 v = make_float2(c0 * oscale + sparam[cl],
                                           c1 * oscale + sparam[cl + 1]);
                    *reinterpret_cast<float2*>(Cf + (size_t)gi * ldc + gj) = v;
                }
            }
        }
    }
}

// ---------------- launcher ---------------------------------------------------------
extern "C" void kernel_launch(void* const* d_in, const int* in_sizes, int n_in,
                              void* d_out, int out_size) {
    const float* x       = (const float*)d_in[0];
    const float* U_real  = (const float*)d_in[1];
    const float* U_imag  = (const float*)d_in[2];
    const float* S       = (const float*)d_in[3];
    const float* Vt_real = (const float*)d_in[4];
    const float* Vt_imag = (const float*)d_in[5];
    const float* bias    = (const float*)d_in[6];
    float* out           = (float*)d_out;

#define GA(v, s) void* v; cudaGetSymbolAddress(&v, s)
    GA(XQ, g_XQ); GA(BQ, g_BQ); GA(GH, g_GH); GA(TF, g_TF);
    GA(VTh, g_VTh); GA(Uh, g_Uh);
    GA(Yh, g_Yh); GA(Zh, g_Zh);
    GA(T32, g_T32);
#undef GA

    constexpr int SMEM = 3 * (16384 + 64 * 128);  // 73728 (3-stage ring)
    cudaFuncSetAttribute(hmma_gemm<64, 0>, cudaFuncAttributeMaxDynamicSharedMemorySize, SMEM);
    cudaFuncSetAttribute(hmma_gemm<64, 1>, cudaFuncAttributeMaxDynamicSharedMemorySize, SMEM);

    typedef const __half* HP;
    const size_t PX = 1024ull * KQ;
    const size_t PB = 512ull * KQ;
    constexpr float DESCALE20 = 1.0f / 1048576.0f;  // 2^-20

    // ---- ALL prep in one launch ----
    prep_kernel<<<PB_U, 256>>>(x, U_real, U_imag, S, Vt_real, Vt_imag,
                               (__half*)BQ, (__half*)GH, (__half*)XQ,
                               (__half*)VTh, (__half*)Uh);

    // ---- G1: Y(2^10) = 4 quarter GEMMs (1024 x 2048, K=1088) ----
    {
        GP4 gp;
        HP xq = (HP)XQ, bq = (HP)BQ;
        for (int q = 0; q < 4; q++) {
            gp.Ah[q] = xq + q * PX;
            gp.Bh[q] = bq + q * PB;
        }
        hmma_gemm<64, 0><<<dim3(32, 8), 128, SMEM>>>(
            gp, 8, KQ, nullptr, 1.0f, (__half*)Yh, nullptr, 2048);
    }
    // ---- G2: T32(2^10) = Y @ (S*VTperm)^T (1024 x 2048, K=2048), fp32 out ----
    {
        GP4 gp;
        for (int q = 0; q < 4; q++) {
            gp.Ah[q] = (HP)Yh; gp.Bh[q] = (HP)VTh;
        }
        hmma_gemm<64, 1><<<dim3(32, 8), 128, SMEM>>>(
            gp, 32, 2048, nullptr, 1.0f, nullptr, (float*)T32, 2048);
    }
    // ---- fold T ----
    foldT_kernel<<<(1024 * 136 + 255) / 256, 256>>>((const float*)T32, (__half*)TF);
    // ---- G3: Z(2^20) = 2 half GEMMs (1024 x 1024, K=1088) ----
    {
        GP4 gp;
        HP tf = (HP)TF, gh = (HP)GH;
        for (int q = 0; q < 4; q++) {
            int h2 = (q > 1) ? 1 : q;
            gp.Ah[q] = tf + h2 * PX;
            gp.Bh[q] = gh + h2 * PB;
        }
        hmma_gemm<64, 0><<<dim3(16, 8), 128, SMEM>>>(
            gp, 8, KQ, nullptr, 1.0f, (__half*)Zh, nullptr, 1024);
    }
    // ---- G4: out = Z @ U^T * 2^-20 + bias (1024 x 4096, K=1024) ----
    {
        GP4 gp;
        for (int q = 0; q < 4; q++) {
            gp.Ah[q] = (HP)Zh; gp.Bh[q] = (HP)Uh;
        }
        hmma_gemm<64, 1><<<dim3(64, 8), 128, SMEM>>>(
            gp, 64, 1024, bias, DESCALE20, nullptr, (float*)out, 4096);
    }
}

// round 17
// speedup vs baseline: 1.1797x; 1.0550x over previous
#include <cuda_runtime.h>
#include <cuda_fp16.h>
#include <cstdint>
#include <cstddef>
#include <math.h>

// ============================================================================
// out = x @ (irfft(U)·S @ irfft(V)).T + bias
// G1 radix-4 folded, G3 radix-2 folded, G2 B-rows pre-folded (foldT fused
// away). Plain fp16 GEMMs, fp32 accum (validated error ~5.6e-4). Scaling:
// bases x2^10, Y/TF at 2^10, Z at 2^20, G4 epilogue x2^-20.
// GEMM: 4-stage cp.async ring, ONE sync+wait per chunk PAIR.
// ============================================================================

static constexpr double PI_D = 3.141592653589793238462643383279502884;

// ---------------- device scratch ---------------------------------------------
__device__ __align__(128) __half g_XQ[4ull * 1024 * 1088];
__device__ __align__(128) __half g_BQ[4ull * 512 * 1088];
__device__ __align__(128) __half g_GH[2ull * 512 * 1088];
__device__ __align__(128) __half g_WF[2ull * 1088 * 2048];   // folded G2 B rows
__device__ __align__(128) __half g_TF[2ull * 1024 * 1088];
__device__ __align__(128) __half g_Uh[4096ull * 1024];
__device__ __align__(128) __half g_Yh[1024ull * 2048];
__device__ __align__(128) __half g_Zh[1024ull * 1024];

static constexpr int KQ = 1088;

// ---------------- helpers ------------------------------------------------------
__device__ __forceinline__ uint32_t s2u(const void* p) {
    uint32_t a;
    asm("{ .reg .u64 t; cvta.to.shared.u64 t, %1; cvt.u32.u64 %0, t; }"
        : "=r"(a) : "l"(p));
    return a;
}
__device__ __forceinline__ void cpa16(uint32_t dst, const void* src) {
    asm volatile("cp.async.cg.shared.global [%0], [%1], 16;"
                 :: "r"(dst), "l"(src) : "memory");
}
#define CP_COMMIT() asm volatile("cp.async.commit_group;" ::: "memory")
#define CP_WAIT0()  asm volatile("cp.async.wait_group 0;" ::: "memory")

__device__ __forceinline__ uint32_t swz(uint32_t r, uint32_t cb) {
    return r * 128u + (cb ^ ((r & 7u) << 4));
}
__device__ __forceinline__ uint32_t pack_h(__half a, __half b) {
    __half2 t = __halves2half2(a, b);
    return *reinterpret_cast<uint32_t*>(&t);
}
__device__ __forceinline__ void pack8h(const float* v, uint4& H) {
    __half h[8];
#pragma unroll
    for (int e = 0; e < 8; e++) h[e] = __float2half_rn(v[e]);
    H = *reinterpret_cast<uint4*>(h);
}
#define LDSM4(r, addr)                                                        \
    asm volatile("ldmatrix.sync.aligned.m8n8.x4.shared.b16 {%0,%1,%2,%3}, [%4];" \
                 : "=r"((r)[0]), "=r"((r)[1]), "=r"((r)[2]), "=r"((r)[3])     \
                 : "r"(addr))
#define HMMA(acc, a, b0, b1)                                                  \
    asm volatile(                                                             \
        "mma.sync.aligned.m16n8k16.row.col.f32.f16.f16.f32 "                  \
        "{%0,%1,%2,%3}, {%4,%5,%6,%7}, {%8,%9}, {%0,%1,%2,%3};"               \
        : "+f"((acc)[0]), "+f"((acc)[1]), "+f"((acc)[2]), "+f"((acc)[3])      \
        : "r"((a)[0]), "r"((a)[1]), "r"((a)[2]), "r"((a)[3]), "r"(b0), "r"(b1))

// ---------------- fused prep kernel ---------------------------------------------
// blocks: [0,1088) BQ bases | [1088,1632) GH bases | [1632,2176) foldX
//         [2176,3264) fold-W (one j-row per block) | [3264,5312) splitU
static constexpr int PB_B1 = 1088;
static constexpr int PB_B2 = PB_B1 + 544;
static constexpr int PB_B3 = PB_B2 + 544;
static constexpr int PB_B4 = PB_B3 + 1088;
static constexpr int PB_TOT = PB_B4 + 2048;

__global__ void __launch_bounds__(256)
prep_kernel(const float* __restrict__ x,
            const float* __restrict__ U_real, const float* __restrict__ U_imag,
            const float* __restrict__ S,
            const float* __restrict__ Vt_real, const float* __restrict__ Vt_imag,
            __half* __restrict__ BQ, __half* __restrict__ GH,
            __half* __restrict__ XQ,
            __half* __restrict__ WF, __half* __restrict__ Uh) {
    const int blk = blockIdx.x;
    const int thr = threadIdx.x;

    if (blk < PB_B2) {
        // ---- trig bases, scaled x2^10 ----
        bool isBQ = (blk < PB_B1);
        int u = (isBQ ? blk : (blk - PB_B1)) * 256 + thr;
        int jv8 = u % 136;
        int kk = (u / 136) & 511;
        int z = u / (136 * 512);
        if (!isBQ && z >= 2) return;
        if (isBQ && z >= 4) return;
        int jv = jv8 * 8;
        int n = isBQ ? 4096 : 2048;
        int k = isBQ ? (2 * kk + (z & 1)) : kk;
        bool is_cos = isBQ ? (z < 2) : (z == 0);
        float ww = ((k == 0) ? 1024.0f : 2048.0f) / (float)n;  // x2^10
        float step = (float)(2.0 * PI_D / n);
        int mask = n - 1;
        float v[8];
#pragma unroll
        for (int e = 0; e < 8; e++) {
            int j = jv + e;
            float w = 0.0f;
            if (j <= 1024) {
                int idx = (j * k) & mask;
                float sv, cv;
                sincosf(step * (float)idx, &sv, &cv);
                w = is_cos ? ww * cv : -ww * sv;
            }
            v[e] = w;
        }
        uint4 H;
        pack8h(v, H);
        __half* base = isBQ ? BQ : GH;
        size_t off = ((size_t)z * 512 + kk) * KQ + jv;
        *reinterpret_cast<uint4*>(base + off) = H;
    } else if (blk < PB_B3) {
        // ---- foldX ----
        int t = (blk - PB_B2) * 256 + thr;
        if (t >= 1024 * 136) return;
        int r = t / 136;
        int jv = (t % 136) * 8;
        const float* xr = x + (size_t)r * 4096;
        float vee[8], veo[8], voe[8], voo[8];
#pragma unroll
        for (int e = 0; e < 8; e++) {
            int j = jv + e;
            float ee = 0, eo = 0, oe = 0, oo = 0;
            if (j == 0) {
                float a = xr[0], nq = xr[2048];
                ee = a + nq; eo = a - nq;
            } else if (j < 1024) {
                float a = xr[j], b = xr[4096 - j], c = xr[2048 - j], d = xr[2048 + j];
                float E = a + b, O = a - b, E2 = c + d, O2 = c - d;
                ee = E + E2; eo = E - E2; oe = O - O2; oo = O + O2;
            } else if (j == 1024) {
                float a = xr[1024], b = xr[3072];
                float E = a + b, O = a - b;
                ee = E; eo = E; oe = O; oo = O;
            }
            vee[e] = ee; veo[e] = eo; voe[e] = oe; voo[e] = oo;
        }
        uint4 H;
        size_t rb = (size_t)r * KQ + jv;
        size_t plane = 1024ull * KQ;
        pack8h(vee, H);
        *reinterpret_cast<uint4*>(XQ + 0 * plane + rb) = H;
        pack8h(veo, H);
        *reinterpret_cast<uint4*>(XQ + 1 * plane + rb) = H;
        pack8h(voe, H);
        *reinterpret_cast<uint4*>(XQ + 2 * plane + rb) = H;
        pack8h(voo, H);
        *reinterpret_cast<uint4*>(XQ + 3 * plane + rb) = H;
    } else if (blk < PB_B4) {
        // ---- fold-W: Wc[j] = W[j]+W[2048-j], Ws[j] = W[j]-W[2048-j]
        //      (W[l] = S[l] * VtPerm[l]); rows j >= 1025 are zero.
        int j = blk - PB_B3;                 // 0..1087
        int c0 = thr * 8;                    // K offset (0..2047)
        size_t PLW = 1088ull * 2048;
        float vc[8], vs[8];
        if (j >= 1025) {
#pragma unroll
            for (int e = 0; e < 8; e++) { vc[e] = 0.0f; vs[e] = 0.0f; }
        } else {
            int q = c0 >> 9;
            const float* base1 = ((q < 2) ? Vt_real : Vt_imag);
            const float* sr1 = base1 + (size_t)j * 1024;
            float s1 = S[j];
            bool pair = (j >= 1 && j <= 1023);
            int m = 2048 - j;
            const float* sr2 = pair ? base1 + (size_t)m * 1024 : sr1;
            float s2 = pair ? S[m] : 0.0f;
#pragma unroll
            for (int e = 0; e < 8; e++) {
                int k = (((c0 & 511) + e) << 1) | (q & 1);
                float a = sr1[k] * s1;
                float b = pair ? sr2[k] * s2 : 0.0f;
                vc[e] = a + b;
                vs[e] = pair ? (a - b) : 0.0f;
            }
        }
        uint4 H;
        pack8h(vc, H);
        *reinterpret_cast<uint4*>(WF + (size_t)j * 2048 + c0) = H;
        pack8h(vs, H);
        *reinterpret_cast<uint4*>(WF + PLW + (size_t)j * 2048 + c0) = H;
    } else {
        // ---- splitU ----
        int t = (blk - PB_B4) * 256 + thr;
        if (t >= 4096 * 128) return;
        int r = t >> 7;
        int c0 = (t & 127) * 8;
        const float* src = ((c0 >> 9) ? U_imag : U_real) + (size_t)r * 512;
        float v[8];
#pragma unroll
        for (int e = 0; e < 8; e++) v[e] = src[(c0 & 511) + e];
        uint4 H;
        pack8h(v, H);
        *reinterpret_cast<uint4*>(Uh + (size_t)r * 1024 + c0) = H;
    }
}

// ---------------- HMMA GEMM (single pass, 4-stage ring, 1 sync per pair) ---------
struct GP4 {
    const __half* Ah[4];
    const __half* Bh[4];
    __half* Co[4];         // EPI=0 output base per set (col = jb*BN local)
};

template <int BN, int EPI>
__global__ void __launch_bounds__(128, 2)
hmma_gemm(GP4 gp, int bpq, int K,
          const float* __restrict__ bias, float oscale,
          float* __restrict__ Cf, int ldc) {
    constexpr int NW = BN / 32;
    constexpr int ATILE = 16384;
    constexpr int BTILE = BN * 128;
    constexpr uint32_t STAGE = ATILE + BTILE;   // 24576 for BN=64
    constexpr int NTHR = 128;

    extern __shared__ char dyn[];
    __shared__ float sparam[BN];

    const int tid = threadIdx.x;
    const int wid = tid >> 5;
    const int lane = tid & 31;
    const int setId = blockIdx.x / bpq;
    const int jb = blockIdx.x % bpq;
    const int i0 = blockIdx.y * 128;
    const uint32_t sbase = s2u(dyn);

    const __half* Ah = gp.Ah[setId];
    const __half* Bh = gp.Bh[setId];

    if (EPI == 1)
        for (int i = tid; i < BN; i += NTHR)
            sparam[i] = bias ? bias[blockIdx.x * BN + i] : 0.0f;

    const int nch = K >> 6;

    const int arow = lane & 15;
    const int acol = lane & 16;
    const int brow = (lane & 7) + ((lane & 16) >> 1);
    const int bcol = (lane & 8) << 1;

    const int m0 = (wid / NW) * 64;
    const int n0 = (wid % NW) * 32;

    float acc[4][4][4];
#pragma unroll
    for (int a = 0; a < 4; a++)
#pragma unroll
        for (int b = 0; b < 4; b++)
#pragma unroll
            for (int c = 0; c < 4; c++) acc[a][b][c] = 0.0f;

    auto load_stage = [&](int c, int stg) {
        const uint32_t sb = sbase + (uint32_t)stg * STAGE;
        const int k0 = c << 6;
        const __half* gAh = Ah + (size_t)i0 * K + k0;
        const __half* gBh = Bh + (size_t)jb * BN * K + k0;
#pragma unroll
        for (int it = 0; it < 8; it++) {
            int s = tid + it * NTHR;
            int r = s >> 3, cc = s & 7;
            cpa16(sb + swz(r, cc * 16), gAh + (size_t)r * K + cc * 8);
        }
#pragma unroll
        for (int it = 0; it < BN * 8 / NTHR; it++) {
            int s = tid + it * NTHR;
            int r = s >> 3, cc = s & 7;
            cpa16(sb + ATILE + swz(r, cc * 16), gBh + (size_t)r * K + cc * 8);
        }
    };

    auto compute_chunk = [&](int c) {
        const uint32_t sb = sbase + (uint32_t)(c & 3) * STAGE;
        const uint32_t sAh = sb;
        const uint32_t sBh = sb + ATILE;
#pragma unroll
        for (int kk = 0; kk < 4; kk++) {
            const uint32_t kb = kk * 32;
            uint32_t aH[4][4], bH[2][4];
#pragma unroll
            for (int mi = 0; mi < 4; mi++)
                LDSM4(aH[mi], sAh + swz(m0 + mi * 16 + arow, kb + acol));
#pragma unroll
            for (int nb = 0; nb < 2; nb++)
                LDSM4(bH[nb], sBh + swz(n0 + nb * 16 + brow, kb + bcol));
#pragma unroll
            for (int mi = 0; mi < 4; mi++)
#pragma unroll
                for (int ni = 0; ni < 4; ni++)
                    HMMA(acc[mi][ni], aH[mi],
                         bH[ni >> 1][(ni & 1) * 2], bH[ni >> 1][(ni & 1) * 2 + 1]);
        }
    };

    // prologue: pair 0
    load_stage(0, 0);
    if (nch > 1) load_stage(1, 1);
    CP_COMMIT();

    for (int c0 = 0; c0 < nch; c0 += 2) {
        CP_WAIT0();
        __syncthreads();
        // issue next pair (targets stages freed by the sync above)
        if (c0 + 2 < nch) load_stage(c0 + 2, (c0 + 2) & 3);
        if (c0 + 3 < nch) load_stage(c0 + 3, (c0 + 3) & 3);
        CP_COMMIT();
        compute_chunk(c0);
        if (c0 + 1 < nch) compute_chunk(c0 + 1);
    }

    // ---- epilogue ----
    const int tg = lane >> 2;
    const int ti = lane & 3;
    __half* Co = gp.Co[setId];
#pragma unroll
    for (int mi = 0; mi < 4; mi++) {
#pragma unroll
        for (int ni = 0; ni < 4; ni++) {
            const int cl = n0 + ni * 8 + 2 * ti;
#pragma unroll
            for (int h = 0; h < 2; h++) {
                const int gi = i0 + m0 + mi * 16 + tg + h * 8;
                const float c0 = acc[mi][ni][2 * h];
                const float c1 = acc[mi][ni][2 * h + 1];
                if (EPI == 0) {
                    size_t off = (size_t)gi * ldc + jb * BN + cl;
                    *reinterpret_cast<uint32_t*>(Co + off) =
                        pack_h(__float2half_rn(c0), __float2half_rn(c1));
                } else {
                    float2 v = make_float2(c0 * oscale + sparam[cl],
                                           c1 * oscale + sparam[cl + 1]);
                    size_t off = (size_t)gi * ldc + blockIdx.x * BN + cl;
                    *reinterpret_cast<float2*>(Cf + off) = v;
                }
            }
        }
    }
}

// ---------------- launcher ---------------------------------------------------------
extern "C" void kernel_launch(void* const* d_in, const int* in_sizes, int n_in,
                              void* d_out, int out_size) {
    const float* x       = (const float*)d_in[0];
    const float* U_real  = (const float*)d_in[1];
    const float* U_imag  = (const float*)d_in[2];
    const float* S       = (const float*)d_in[3];
    const float* Vt_real = (const float*)d_in[4];
    const float* Vt_imag = (const float*)d_in[5];
    const float* bias    = (const float*)d_in[6];
    float* out           = (float*)d_out;

#define GA(v, s) void* v; cudaGetSymbolAddress(&v, s)
    GA(XQ, g_XQ); GA(BQ, g_BQ); GA(GH, g_GH); GA(WF, g_WF); GA(TF, g_TF);
    GA(Uh, g_Uh); GA(Yh, g_Yh); GA(Zh, g_Zh);
#undef GA

    constexpr int SMEM = 4 * 24576;  // 98304 (4-stage ring)
    cudaFuncSetAttribute(hmma_gemm<64, 0>, cudaFuncAttributeMaxDynamicSharedMemorySize, SMEM);
    cudaFuncSetAttribute(hmma_gemm<64, 1>, cudaFuncAttributeMaxDynamicSharedMemorySize, SMEM);

    typedef const __half* HP;
    typedef __half* HPm;
    const size_t PX = 1024ull * KQ;       // XQ / TF plane
    const size_t PB = 512ull * KQ;        // basis plane
    const size_t PLW = 1088ull * 2048;    // WF plane
    constexpr float DESCALE20 = 1.0f / 1048576.0f;  // 2^-20

    // ---- ALL prep in one launch ----
    prep_kernel<<<PB_TOT, 256>>>(x, U_real, U_imag, S, Vt_real, Vt_imag,
                                 (__half*)BQ, (__half*)GH, (__half*)XQ,
                                 (__half*)WF, (__half*)Uh);

    // ---- G1: Y(2^10) = 4 quarter GEMMs (1024 x 2048, K=1088) ----
    {
        GP4 gp;
        for (int q = 0; q < 4; q++) {
            gp.Ah[q] = (HP)XQ + q * PX;
            gp.Bh[q] = (HP)BQ + q * PB;
            gp.Co[q] = (HPm)Yh + q * 512;
        }
        hmma_gemm<64, 0><<<dim3(32, 8), 128, SMEM>>>(
            gp, 8, KQ, nullptr, 1.0f, nullptr, 2048);
    }
    // ---- G2: TF(2^10) = Y @ Wfold^T  (1024 x 2176, K=2048), fp16 out ----
    {
        GP4 gp;
        for (int q = 0; q < 4; q++) {
            int s = (q > 1) ? 1 : q;
            gp.Ah[q] = (HP)Yh;
            gp.Bh[q] = (HP)WF + s * PLW;
            gp.Co[q] = (HPm)TF + s * PX;
        }
        hmma_gemm<64, 0><<<dim3(34, 8), 128, SMEM>>>(
            gp, 17, 2048, nullptr, 1.0f, nullptr, KQ);
    }
    // ---- G3: Z(2^20) = 2 half GEMMs (1024 x 1024, K=1088) ----
    {
        GP4 gp;
        for (int q = 0; q < 4; q++) {
            int h2 = (q > 1) ? 1 : q;
            gp.Ah[q] = (HP)TF + h2 * PX;
            gp.Bh[q] = (HP)GH + h2 * PB;
            gp.Co[q] = (HPm)Zh + h2 * 512;
        }
        hmma_gemm<64, 0><<<dim3(16, 8), 128, SMEM>>>(
            gp, 8, KQ, nullptr, 1.0f, nullptr, 1024);
    }
    // ---- G4: out = Z @ U^T * 2^-20 + bias (1024 x 4096, K=1024) ----
    {
        GP4 gp;
        for (int q = 0; q < 4; q++) {
            gp.Ah[q] = (HP)Zh;
            gp.Bh[q] = (HP)Uh;
            gp.Co[q] = nullptr;
        }
        hmma_gemm<64, 1><<<dim3(64, 8), 128, SMEM>>>(
            gp, 64, 1024, bias, DESCALE20, (float*)out, 4096);
    }
}